// round 1
// baseline (speedup 1.0000x reference)
#include <cuda_runtime.h>
#include <cuda_bf16.h>

#define D 64
#define NUM_REL 32
#define MAXB 131072

// Scratch (static device globals — no allocations allowed)
__device__ int g_counts[NUM_REL];
__device__ int g_idx[NUM_REL * MAXB];   // 16 MB bucket storage

// ---------------------------------------------------------------------------
// Kernel 0: reset per-relation counters (must run every launch: graph replay)
// ---------------------------------------------------------------------------
__global__ void zero_counts_kernel() {
    if (threadIdx.x < NUM_REL) g_counts[threadIdx.x] = 0;
}

// ---------------------------------------------------------------------------
// Kernel 1: bucket sample ids by relation.
// smem-aggregated counting, then one global atomicAdd per relation per block.
// ---------------------------------------------------------------------------
__global__ void bucket_kernel(const int* __restrict__ rels, int B) {
    __shared__ int s_count[NUM_REL];
    __shared__ int s_base[NUM_REL];
    int t = threadIdx.x;
    if (t < NUM_REL) s_count[t] = 0;
    __syncthreads();

    int i = blockIdx.x * blockDim.x + t;
    int r = 0, lp = 0;
    bool valid = (i < B);
    if (valid) {
        r  = rels[i];
        lp = atomicAdd(&s_count[r], 1);
    }
    __syncthreads();
    if (t < NUM_REL) s_base[t] = atomicAdd(&g_counts[t], s_count[t]);
    __syncthreads();
    if (valid) g_idx[r * MAXB + s_base[r] + lp] = i;
}

// ---------------------------------------------------------------------------
// Kernel 2: per-relation bilinear scores.
// blockIdx.x = relation; relation matrix cached in smem; each warp processes
// tiles of 32 samples so every LDS of R is a 32-lane broadcast.
// score_b = sum_e e2[e] * (sum_d e1[d] * R[d][e])
// ---------------------------------------------------------------------------
#define THREADS 128
#define WARPS_PER_BLOCK (THREADS / 32)
#define BLOCKS_PER_REL 16

__global__ void __launch_bounds__(THREADS)
score_kernel(const float* __restrict__ e1g,
             const float* __restrict__ e2g,
             const float* __restrict__ relw,
             float* __restrict__ out)
{
    __shared__ float sR[D * D];   // 16 KB

    const int r = blockIdx.x;

    // cooperative load of this relation's matrix (4096 floats)
    {
        const float4* src = reinterpret_cast<const float4*>(relw + r * (D * D));
        float4* dst = reinterpret_cast<float4*>(sR);
        #pragma unroll
        for (int i = threadIdx.x; i < (D * D) / 4; i += THREADS) dst[i] = src[i];
    }
    __syncthreads();

    const int count  = g_counts[r];
    const int ntiles = (count + 31) >> 5;
    const int lane   = threadIdx.x & 31;
    const int warp   = threadIdx.x >> 5;
    const int wglob  = blockIdx.y * WARPS_PER_BLOCK + warp;
    const int wstr   = gridDim.y * WARPS_PER_BLOCK;
    const int* __restrict__ idx = g_idx + r * MAXB;

    for (int tile = wglob; tile < ntiles; tile += wstr) {
        const int s     = (tile << 5) + lane;
        const bool valid = (s < count);
        const int b     = valid ? idx[s] : 0;

        const float4* p1 = reinterpret_cast<const float4*>(e1g) + b * (D / 4);
        const float4* p2 = reinterpret_cast<const float4*>(e2g) + b * (D / 4);

        float score = 0.0f;

        #pragma unroll 1
        for (int ec = 0; ec < 4; ec++) {          // 16-column chunk of e
            float4 u0 = p2[ec * 4 + 0];
            float4 u1 = p2[ec * 4 + 1];
            float4 u2 = p2[ec * 4 + 2];
            float4 u3 = p2[ec * 4 + 3];

            float tmp[16];
            #pragma unroll
            for (int j = 0; j < 16; j++) tmp[j] = 0.0f;

            #pragma unroll 1
            for (int dc = 0; dc < 4; dc++) {      // 16-row chunk of d
                float4 a0 = p1[dc * 4 + 0];
                float4 a1 = p1[dc * 4 + 1];
                float4 a2 = p1[dc * 4 + 2];
                float4 a3 = p1[dc * 4 + 3];
                float av[16] = {a0.x, a0.y, a0.z, a0.w,
                                a1.x, a1.y, a1.z, a1.w,
                                a2.x, a2.y, a2.z, a2.w,
                                a3.x, a3.y, a3.z, a3.w};

                const float4* rbase =
                    reinterpret_cast<const float4*>(sR + (dc * 16) * D + ec * 16);

                #pragma unroll
                for (int dd = 0; dd < 16; dd++) {
                    const float a = av[dd];
                    // broadcast loads: all 32 lanes read the same smem address
                    float4 q0 = rbase[dd * (D / 4) + 0];
                    float4 q1 = rbase[dd * (D / 4) + 1];
                    float4 q2 = rbase[dd * (D / 4) + 2];
                    float4 q3 = rbase[dd * (D / 4) + 3];
                    tmp[ 0] = fmaf(a, q0.x, tmp[ 0]);
                    tmp[ 1] = fmaf(a, q0.y, tmp[ 1]);
                    tmp[ 2] = fmaf(a, q0.z, tmp[ 2]);
                    tmp[ 3] = fmaf(a, q0.w, tmp[ 3]);
                    tmp[ 4] = fmaf(a, q1.x, tmp[ 4]);
                    tmp[ 5] = fmaf(a, q1.y, tmp[ 5]);
                    tmp[ 6] = fmaf(a, q1.z, tmp[ 6]);
                    tmp[ 7] = fmaf(a, q1.w, tmp[ 7]);
                    tmp[ 8] = fmaf(a, q2.x, tmp[ 8]);
                    tmp[ 9] = fmaf(a, q2.y, tmp[ 9]);
                    tmp[10] = fmaf(a, q2.z, tmp[10]);
                    tmp[11] = fmaf(a, q2.w, tmp[11]);
                    tmp[12] = fmaf(a, q3.x, tmp[12]);
                    tmp[13] = fmaf(a, q3.y, tmp[13]);
                    tmp[14] = fmaf(a, q3.z, tmp[14]);
                    tmp[15] = fmaf(a, q3.w, tmp[15]);
                }
            }

            score = fmaf(tmp[ 0], u0.x, score);
            score = fmaf(tmp[ 1], u0.y, score);
            score = fmaf(tmp[ 2], u0.z, score);
            score = fmaf(tmp[ 3], u0.w, score);
            score = fmaf(tmp[ 4], u1.x, score);
            score = fmaf(tmp[ 5], u1.y, score);
            score = fmaf(tmp[ 6], u1.z, score);
            score = fmaf(tmp[ 7], u1.w, score);
            score = fmaf(tmp[ 8], u2.x, score);
            score = fmaf(tmp[ 9], u2.y, score);
            score = fmaf(tmp[10], u2.z, score);
            score = fmaf(tmp[11], u2.w, score);
            score = fmaf(tmp[12], u3.x, score);
            score = fmaf(tmp[13], u3.y, score);
            score = fmaf(tmp[14], u3.z, score);
            score = fmaf(tmp[15], u3.w, score);
        }

        if (valid) out[b] = score;
    }
}

// ---------------------------------------------------------------------------
// kernel_launch
// inputs (metadata order): embeds1 [B*64] f32, embeds2 [B*64] f32,
//                          rels [B] i32, rel_embeds [32*4096] f32
// output: [B] f32
// ---------------------------------------------------------------------------
extern "C" void kernel_launch(void* const* d_in, const int* in_sizes, int n_in,
                              void* d_out, int out_size) {
    const float* e1   = (const float*)d_in[0];
    const float* e2   = (const float*)d_in[1];
    const int*   rels = (const int*)d_in[2];
    const float* relw = (const float*)d_in[3];
    float* out = (float*)d_out;

    const int B = in_sizes[0] / D;

    zero_counts_kernel<<<1, 32>>>();
    bucket_kernel<<<(B + 255) / 256, 256>>>(rels, B);

    dim3 grid(NUM_REL, BLOCKS_PER_REL);
    score_kernel<<<grid, THREADS>>>(e1, e2, relw, out);
}

// round 3
// speedup vs baseline: 1.4280x; 1.4280x over previous
#include <cuda_runtime.h>
#include <cuda_bf16.h>

#define D 64
#define NUM_REL 32
#define MAXB 131072

// Scratch (static device globals — no allocations allowed)
__device__ int g_counts[NUM_REL];
__device__ int g_idx[NUM_REL * MAXB];   // 16 MB bucket storage

// ---------------------------------------------------------------------------
// f32x2 packed-math helpers (sm_103a FFMA2 — PTX-only)
// ---------------------------------------------------------------------------
__device__ __forceinline__ unsigned long long pack2(float x) {
    unsigned long long r;
    asm("mov.b64 %0, {%1, %1};" : "=l"(r) : "r"(__float_as_uint(x)));
    return r;
}
__device__ __forceinline__ unsigned long long fma2(unsigned long long a,
                                                   unsigned long long b,
                                                   unsigned long long c) {
    unsigned long long d;
    asm("fma.rn.f32x2 %0, %1, %2, %3;" : "=l"(d) : "l"(a), "l"(b), "l"(c));
    return d;
}
__device__ __forceinline__ float hsum2(unsigned long long v) {
    unsigned int lo, hi;
    asm("mov.b64 {%0, %1}, %2;" : "=r"(lo), "=r"(hi) : "l"(v));
    return __uint_as_float(lo) + __uint_as_float(hi);
}

// ---------------------------------------------------------------------------
// Kernel 0: reset per-relation counters (must run every launch: graph replay)
// ---------------------------------------------------------------------------
__global__ void zero_counts_kernel() {
    if (threadIdx.x < NUM_REL) g_counts[threadIdx.x] = 0;
}

// ---------------------------------------------------------------------------
// Kernel 1: bucket sample ids by relation.
// ---------------------------------------------------------------------------
__global__ void bucket_kernel(const int* __restrict__ rels, int B) {
    __shared__ int s_count[NUM_REL];
    __shared__ int s_base[NUM_REL];
    int t = threadIdx.x;
    if (t < NUM_REL) s_count[t] = 0;
    __syncthreads();

    int i = blockIdx.x * blockDim.x + t;
    int r = 0, lp = 0;
    bool valid = (i < B);
    if (valid) {
        r  = rels[i];
        lp = atomicAdd(&s_count[r], 1);
    }
    __syncthreads();
    if (t < NUM_REL) s_base[t] = atomicAdd(&g_counts[t], s_count[t]);
    __syncthreads();
    if (valid) g_idx[r * MAXB + s_base[r] + lp] = i;
}

// ---------------------------------------------------------------------------
// Kernel 2: per-relation bilinear scores with packed f32x2 FMAs.
// blockIdx.x = relation; R cached in smem; all 32 lanes of a warp share the
// same R row per step -> every LDS.128 is a conflict-free broadcast.
// Single pass over d: tmp[32] (f32x2) holds all 64 e-column accumulators;
// e1 and e2 are each read from global exactly once per sample.
// ---------------------------------------------------------------------------
#define THREADS 128
#define WARPS_PER_BLOCK (THREADS / 32)
#define BLOCKS_PER_REL 32

// one R row (64 floats = 16 ulonglong2):
// tmp[2j] += (a,a) * R[row][4j..4j+1]; tmp[2j+1] += (a,a) * R[row][4j+2..4j+3]
__device__ __forceinline__ void row_fma(unsigned long long* __restrict__ tmp,
                                        const ulonglong2* __restrict__ rrow,
                                        float a) {
    unsigned long long a2 = pack2(a);
    #pragma unroll
    for (int j = 0; j < 16; j++) {
        ulonglong2 q = rrow[j];
        tmp[2 * j]     = fma2(a2, q.x, tmp[2 * j]);
        tmp[2 * j + 1] = fma2(a2, q.y, tmp[2 * j + 1]);
    }
}

#define ROW_STRIDE_U2 16   // 64 floats per row = 16 ulonglong2

__global__ void __launch_bounds__(THREADS, 4)
score_kernel(const float* __restrict__ e1g,
             const float* __restrict__ e2g,
             const float* __restrict__ relw,
             float* __restrict__ out)
{
    __shared__ float sR[D * D];   // 16 KB

    const int r = blockIdx.x;

    // cooperative load of this relation's matrix (4096 floats)
    {
        const float4* src = reinterpret_cast<const float4*>(relw + r * (D * D));
        float4* dst = reinterpret_cast<float4*>(sR);
        #pragma unroll
        for (int i = threadIdx.x; i < (D * D) / 4; i += THREADS) dst[i] = src[i];
    }
    __syncthreads();

    const int count  = g_counts[r];
    const int ntiles = (count + 31) >> 5;
    const int lane   = threadIdx.x & 31;
    const int warp   = threadIdx.x >> 5;
    const int wglob  = blockIdx.y * WARPS_PER_BLOCK + warp;
    const int wstr   = gridDim.y * WARPS_PER_BLOCK;
    const int* __restrict__ idx = g_idx + r * MAXB;

    for (int tile = wglob; tile < ntiles; tile += wstr) {
        const int s      = (tile << 5) + lane;
        const bool valid = (s < count);
        const int b      = valid ? idx[s] : 0;

        const float4* p1 = reinterpret_cast<const float4*>(e1g) + b * (D / 4);

        // 32 packed accumulators = 64 e-columns
        unsigned long long tmp[32];
        #pragma unroll
        for (int j = 0; j < 32; j++) tmp[j] = 0ull;

        float4 a_next = p1[0];
        #pragma unroll 1
        for (int g = 0; g < 16; g++) {          // 4 d-rows per iteration
            float4 a = a_next;
            if (g < 15) a_next = p1[g + 1];     // one-ahead prefetch
            const ulonglong2* rrow =
                reinterpret_cast<const ulonglong2*>(sR + (g * 4) * D);
            row_fma(tmp, rrow + 0 * ROW_STRIDE_U2, a.x);
            row_fma(tmp, rrow + 1 * ROW_STRIDE_U2, a.y);
            row_fma(tmp, rrow + 2 * ROW_STRIDE_U2, a.z);
            row_fma(tmp, rrow + 3 * ROW_STRIDE_U2, a.w);
        }

        // final dot with e2 (packed), 2 accumulator chains
        const ulonglong2* p2 =
            reinterpret_cast<const ulonglong2*>(e2g + b * D);
        unsigned long long acc0 = 0ull, acc1 = 0ull;
        #pragma unroll
        for (int j = 0; j < 16; j++) {
            ulonglong2 u = p2[j];
            acc0 = fma2(tmp[2 * j],     u.x, acc0);
            acc1 = fma2(tmp[2 * j + 1], u.y, acc1);
        }
        float score = hsum2(acc0) + hsum2(acc1);

        if (valid) out[b] = score;
    }
}

// ---------------------------------------------------------------------------
// kernel_launch
// inputs (metadata order): embeds1 [B*64] f32, embeds2 [B*64] f32,
//                          rels [B] i32, rel_embeds [32*4096] f32
// output: [B] f32
// ---------------------------------------------------------------------------
extern "C" void kernel_launch(void* const* d_in, const int* in_sizes, int n_in,
                              void* d_out, int out_size) {
    const float* e1   = (const float*)d_in[0];
    const float* e2   = (const float*)d_in[1];
    const int*   rels = (const int*)d_in[2];
    const float* relw = (const float*)d_in[3];
    float* out = (float*)d_out;

    const int B = in_sizes[0] / D;

    zero_counts_kernel<<<1, 32>>>();
    bucket_kernel<<<(B + 255) / 256, 256>>>(rels, B);

    dim3 grid(NUM_REL, BLOCKS_PER_REL);
    score_kernel<<<grid, THREADS>>>(e1, e2, relw, out);
}